// round 10
// baseline (speedup 1.0000x reference)
#include <cuda_runtime.h>

#define L 64
#define C 7
#define NSTEPS 126   // (L-1)*K, K=2, h=0.5
#define NBPAIR 7     // batches per warp-pair
#define NCTA 293     // 2 pairs per CTA

typedef unsigned long long ull;

__device__ __forceinline__ ull ffma2(ull a, ull b, ull c) {
    ull d;
    asm("fma.rn.f32x2 %0, %1, %2, %3;" : "=l"(d) : "l"(a), "l"(b), "l"(c));
    return d;
}
__device__ __forceinline__ ull pk2(float x, float y) {
    ull r;
    asm("mov.b64 %0, {%1, %2};" : "=l"(r) : "f"(x), "f"(y));
    return r;
}
__device__ __forceinline__ void upk2(ull v, float &x, float &y) {
    asm("mov.b64 {%0, %1}, %2;" : "=f"(x), "=f"(y) : "l"(v));
}
__device__ __forceinline__ float sp_(float x) {
    return fmaxf(x, 0.f) + __logf(1.f + __expf(-fabsf(x)));
}
__device__ __forceinline__ float tanh_(float x) {
    float y;
    asm("tanh.approx.f32 %0, %1;" : "=f"(y) : "f"(x));
    return y;
}

// cubic Hermite derivative: dX = m0 + (diff-m0)*f*(4-3f)
__device__ __forceinline__ float spline_eval(const float* __restrict__ xrow, float t) {
    int idx = (int)t;
    idx = min(idx, L - 2);
    float f = t - (float)idx;
    const float* p = xrow + idx * C;
    float x0 = __ldg(p);
    float x1 = __ldg(p + C);
    float diff = x1 - x0;
    float m0 = diff;
    if (idx > 0) m0 = x0 - __ldg(p - C);
    return fmaf((diff - m0) * f, fmaf(-3.f, f, 4.f), m0);
}

__global__ __launch_bounds__(128, 2)
void cde_kernel(const float* __restrict__ X,      // (4096,64,7)
                const float* __restrict__ Winit,  // (32,7)
                const float* __restrict__ binit,  // (32)
                const float* __restrict__ Wf1,    // (32,32)
                const float* __restrict__ bf1,    // (32)
                const float* __restrict__ Wf2,    // (224,32)
                const float* __restrict__ bf2,    // (224)
                const float* __restrict__ Wo1,    // (16,32)
                const float* __restrict__ bo1,    // (16)
                const float* __restrict__ Wo2,    // (3,16)
                const float* __restrict__ bo2,    // (3)
                float* __restrict__ out)          // (4096,3)
{
    // 4 warps = 2 pairs; pair serves 7 batches (+1 dummy slot); A: c0-3, B: c4-7(pad)
    __shared__ __align__(16) float sZ[4][8][32];        // per-WARP private zs copy
    __shared__ __align__(16) float sH1[4][8][32];       // per-WARP private h1
    __shared__ __align__(16) float sDX[2][3][8][8];     // per-pair spline values
    __shared__ __align__(16) float sPart[2][4][8][32];  // parity-double-buffered partials

    const int tid  = threadIdx.x;
    const int w    = tid >> 5;
    const int lane = tid & 31;          // = h
    const int pair = w >> 1;
    const int isB  = w & 1;
    const int partner = w ^ 1;
    const int gpair = blockIdx.x * 2 + pair;
    const int pairbase = gpair * NBPAIR;

    // ---- Wf2 own c-half, j-pair packed, in registers ----
    ull wreg[4][16];
    float b2[4];
#pragma unroll
    for (int cp = 0; cp < 4; cp++) {
        int cg = isB * 4 + cp;
        if (cg < C) {
            const float2* wp = reinterpret_cast<const float2*>(Wf2 + (lane * C + cg) * 32);
#pragma unroll
            for (int jp = 0; jp < 16; jp++) { float2 v = __ldg(wp + jp); wreg[cp][jp] = pk2(v.x, v.y); }
            b2[cp] = __ldg(bf2 + lane * C + cg);
        } else {
#pragma unroll
            for (int jp = 0; jp < 16; jp++) wreg[cp][jp] = 0ull;
            b2[cp] = 0.f;
        }
    }
    ull rw1[16];
    {
        const float2* p1 = reinterpret_cast<const float2*>(Wf1 + lane * 32);
#pragma unroll
        for (int jp = 0; jp < 16; jp++) { float2 v = __ldg(p1 + jp); rw1[jp] = pk2(v.x, v.y); }
    }
    const float rbf1 = __ldg(bf1 + lane);

    // spline mapping: each warp covers 4 slots (A: 0-3, B: 4-6 + dummy 7)
    const int db = lane >> 3;
    const int dc = lane & 7;
    const int sbatch = min(pairbase + isB * 4 + db, 4095);
    const float* xrow = X + (size_t)sbatch * (L * C) + ((dc < C) ? dc : 0);

    // z0 for ALL 7 batches (redundant in both warps; clamped tail)
    float z[NBPAIR], ksum[NBPAIR];
#pragma unroll
    for (int b = 0; b < NBPAIR; b++) {
        int gb = min(pairbase + b, 4095);
        float acc = __ldg(binit + lane);
        const float* xp = X + (size_t)gb * (L * C);
#pragma unroll
        for (int c = 0; c < C; c++) acc = fmaf(__ldg(xp + c), __ldg(Winit + lane * C + c), acc);
        z[b] = acc;
        ksum[b] = 0.f;
        sZ[w][b][lane] = acc;
    }

    // initial dX(t=0) -> slot 0
    {
        float v = 0.f;
        if (dc < C) v = __ldg(xrow + C) - __ldg(xrow);
        sDX[pair][0][isB * 4 + db][dc] = v;
    }
    __syncthreads();

    int par = 0;
    float t0 = 0.f;
#pragma unroll 1
    for (int i = 0; i < NSTEPS; i++, t0 += 0.5f) {
        // spline: t0+0.25 -> slot 2 ; t0+0.5 -> slot (i+1)&1
        {
            float vb = 0.f, vc = 0.f;
            if (dc < C) {
                vb = spline_eval(xrow, t0 + 0.25f);
                vc = spline_eval(xrow, t0 + 0.5f);
            }
            sDX[pair][2][isB * 4 + db][dc] = vb;
            sDX[pair][(i + 1) & 1][isB * 4 + db][dc] = vc;
        }
        const int slotA = i & 1, slotC = (i + 1) & 1;

#pragma unroll 1
        for (int s = 0; s < 4; s++) {
            const int slot = (s == 0) ? slotA : ((s == 3) ? slotC : 2);

            // ---- mm1 for ALL 7 batches from own private sZ (7 chains) ----
            __syncwarp();
            ull a1[NBPAIR];
#pragma unroll
            for (int b = 0; b < NBPAIR; b++) a1[b] = 0ull;
#pragma unroll
            for (int q = 0; q < 8; q++) {
#pragma unroll
                for (int b = 0; b < NBPAIR; b++) {
                    ulonglong2 zq = *reinterpret_cast<const ulonglong2*>(&sZ[w][b][4 * q]);
                    a1[b] = ffma2(zq.x, rw1[2 * q], a1[b]);
                    a1[b] = ffma2(zq.y, rw1[2 * q + 1], a1[b]);
                }
            }
#pragma unroll
            for (int b = 0; b < NBPAIR; b++) {
                float u, v; upk2(a1[b], u, v);
                sH1[w][b][lane] = sp_(u + v + rbf1);
            }
            __syncwarp();

            // ---- mm2 in batch-PAIRS from private sH1 (own channels) ----
            float* sPw = &sPart[par][w][0][0];
#pragma unroll 1
            for (int bp = 0; bp < 3; bp++) {
                const int bs = 2 * bp;
                const ulonglong2 dxq0 = *reinterpret_cast<const ulonglong2*>(&sDX[pair][slot][bs][isB * 4]);
                const ulonglong2 dxq1 = *reinterpret_cast<const ulonglong2*>(&sDX[pair][slot][bs + 1][isB * 4]);
                const ulonglong2* hp0 = reinterpret_cast<const ulonglong2*>(&sH1[w][bs][0]);
                const ulonglong2* hp1 = reinterpret_cast<const ulonglong2*>(&sH1[w][bs + 1][0]);
                ull a00 = 0ull, a01 = 0ull, a02 = 0ull, a03 = 0ull;
                ull a10 = 0ull, a11 = 0ull, a12 = 0ull, a13 = 0ull;
#pragma unroll
                for (int q = 0; q < 8; q++) {
                    ulonglong2 h0 = hp0[q];
                    ulonglong2 h1 = hp1[q];
                    a00 = ffma2(h0.x, wreg[0][2 * q], a00);
                    a01 = ffma2(h0.x, wreg[1][2 * q], a01);
                    a02 = ffma2(h0.x, wreg[2][2 * q], a02);
                    a03 = ffma2(h0.x, wreg[3][2 * q], a03);
                    a10 = ffma2(h1.x, wreg[0][2 * q], a10);
                    a11 = ffma2(h1.x, wreg[1][2 * q], a11);
                    a12 = ffma2(h1.x, wreg[2][2 * q], a12);
                    a13 = ffma2(h1.x, wreg[3][2 * q], a13);
                    a00 = ffma2(h0.y, wreg[0][2 * q + 1], a00);
                    a01 = ffma2(h0.y, wreg[1][2 * q + 1], a01);
                    a02 = ffma2(h0.y, wreg[2][2 * q + 1], a02);
                    a03 = ffma2(h0.y, wreg[3][2 * q + 1], a03);
                    a10 = ffma2(h1.y, wreg[0][2 * q + 1], a10);
                    a11 = ffma2(h1.y, wreg[1][2 * q + 1], a11);
                    a12 = ffma2(h1.y, wreg[2][2 * q + 1], a12);
                    a13 = ffma2(h1.y, wreg[3][2 * q + 1], a13);
                }
                float u, v;
                float g00, g01, g02, g03, g10, g11, g12, g13;
                upk2(a00, u, v); g00 = tanh_(u + v + b2[0]);
                upk2(a10, u, v); g10 = tanh_(u + v + b2[0]);
                upk2(a01, u, v); g01 = tanh_(u + v + b2[1]);
                upk2(a11, u, v); g11 = tanh_(u + v + b2[1]);
                upk2(a02, u, v); g02 = tanh_(u + v + b2[2]);
                upk2(a12, u, v); g12 = tanh_(u + v + b2[2]);
                upk2(a03, u, v); g03 = tanh_(u + v + b2[3]);
                upk2(a13, u, v); g13 = tanh_(u + v + b2[3]);
                ull e0 = ffma2(pk2(g00, g01), dxq0.x, ffma2(pk2(g02, g03), dxq0.y, 0ull));
                ull e1 = ffma2(pk2(g10, g11), dxq1.x, ffma2(pk2(g12, g13), dxq1.y, 0ull));
                float e0a, e0b, e1a, e1b;
                upk2(e0, e0a, e0b);
                upk2(e1, e1a, e1b);
                sPw[bs * 32 + lane]       = e0a + e0b;
                sPw[(bs + 1) * 32 + lane] = e1a + e1b;
            }
            {   // bs = 6 singleton
                const int bs = 6;
                const ulonglong2 dxq0 = *reinterpret_cast<const ulonglong2*>(&sDX[pair][slot][bs][isB * 4]);
                const ulonglong2* hp0 = reinterpret_cast<const ulonglong2*>(&sH1[w][bs][0]);
                ull a00 = 0ull, a01 = 0ull, a02 = 0ull, a03 = 0ull;
#pragma unroll
                for (int q = 0; q < 8; q++) {
                    ulonglong2 h0 = hp0[q];
                    a00 = ffma2(h0.x, wreg[0][2 * q], a00);
                    a01 = ffma2(h0.x, wreg[1][2 * q], a01);
                    a02 = ffma2(h0.x, wreg[2][2 * q], a02);
                    a03 = ffma2(h0.x, wreg[3][2 * q], a03);
                    a00 = ffma2(h0.y, wreg[0][2 * q + 1], a00);
                    a01 = ffma2(h0.y, wreg[1][2 * q + 1], a01);
                    a02 = ffma2(h0.y, wreg[2][2 * q + 1], a02);
                    a03 = ffma2(h0.y, wreg[3][2 * q + 1], a03);
                }
                float u, v, g0, g1, g2, g3;
                upk2(a00, u, v); g0 = tanh_(u + v + b2[0]);
                upk2(a01, u, v); g1 = tanh_(u + v + b2[1]);
                upk2(a02, u, v); g2 = tanh_(u + v + b2[2]);
                upk2(a03, u, v); g3 = tanh_(u + v + b2[3]);
                ull e = ffma2(pk2(g0, g1), dxq0.x, ffma2(pk2(g2, g3), dxq0.y, 0ull));
                float ea, eb; upk2(e, ea, eb);
                sPw[bs * 32 + lane] = ea + eb;
            }

            // ---- the ONLY pair barrier this stage ----
            asm volatile("bar.sync %0, 64;" :: "r"(pair + 1) : "memory");

            // ---- redundant combine + RK4 for ALL 7 batches (identical in both warps) ----
            const float wk = (s == 1 || s == 2) ? 2.f : 1.f;
            const float an = (s < 2) ? 0.25f : 0.5f;
            const float* pA = &sPart[par][w][0][0];
            const float* pB = &sPart[par][partner][0][0];
#pragma unroll
            for (int b = 0; b < NBPAIR; b++) {
                float kk = pA[b * 32 + lane] + pB[b * 32 + lane];
                ksum[b] = fmaf(wk, kk, ksum[b]);
                float zsv;
                if (s < 3) {
                    zsv = fmaf(an, kk, z[b]);
                } else {
                    z[b] = fmaf(ksum[b], (1.f / 12.f), z[b]);  // h/6
                    ksum[b] = 0.f;
                    zsv = z[b];
                }
                sZ[w][b][lane] = zsv;
            }
            par ^= 1;
        }
    }

    // drain pair before scratch reuse
    asm volatile("bar.sync %0, 64;" :: "r"(pair + 1) : "memory");

    // ---- output head: A writes batches 0-3, B writes 4-6 ----
    const int ob0 = isB * 4;
    const int nk  = isB ? 3 : 4;
    __syncwarp();
    float* so = &sPart[0][w][0][0];   // own-warp scratch [4][32]
    if (lane < 16) {
#pragma unroll
        for (int k = 0; k < 4; k++) {
            if (k < nk) {
                float acc = __ldg(bo1 + lane);
#pragma unroll
                for (int hh = 0; hh < 32; hh++)
                    acc = fmaf(sZ[w][ob0 + k][hh], __ldg(Wo1 + lane * 32 + hh), acc);
                so[k * 32 + lane] = sp_(acc);
            }
        }
    }
    __syncwarp();
    if (lane < 12) {
        int k = lane / 3;
        int jo = lane - 3 * k;
        int gb = pairbase + ob0 + k;
        if (k < nk && gb < 4096) {
            float acc = __ldg(bo2 + jo);
#pragma unroll
            for (int i2 = 0; i2 < 16; i2++)
                acc = fmaf(so[k * 32 + i2], __ldg(Wo2 + jo * 16 + i2), acc);
            out[(size_t)gb * 3 + jo] = acc;
        }
    }
}

extern "C" void kernel_launch(void* const* d_in, const int* in_sizes, int n_in,
                              void* d_out, int out_size) {
    const float* X     = (const float*)d_in[0];
    const float* Winit = (const float*)d_in[1];
    const float* binit = (const float*)d_in[2];
    const float* Wf1   = (const float*)d_in[3];
    const float* bf1   = (const float*)d_in[4];
    const float* Wf2   = (const float*)d_in[5];
    const float* bf2   = (const float*)d_in[6];
    const float* Wo1   = (const float*)d_in[7];
    const float* bo1   = (const float*)d_in[8];
    const float* Wo2   = (const float*)d_in[9];
    const float* bo2   = (const float*)d_in[10];
    float* out = (float*)d_out;

    // 293 CTAs x 128 thr: 2 pairs/CTA x 7 batches = 4102 slots >= 4096 (tail guarded)
    cde_kernel<<<NCTA, 128>>>(X, Winit, binit, Wf1, bf1, Wf2, bf2,
                              Wo1, bo1, Wo2, bo2, out);
}

// round 11
// speedup vs baseline: 1.0240x; 1.0240x over previous
#include <cuda_runtime.h>

#define L 64
#define C 7
#define NSTEPS 126   // (L-1)*K, K=2, h=0.5
#define NCTA 147     // 147 * 28 = 4116 >= 4096

typedef unsigned long long ull;

__device__ __forceinline__ ull ffma2(ull a, ull b, ull c) {
    ull d;
    asm("fma.rn.f32x2 %0, %1, %2, %3;" : "=l"(d) : "l"(a), "l"(b), "l"(c));
    return d;
}
__device__ __forceinline__ ull pk2(float x, float y) {
    ull r;
    asm("mov.b64 %0, {%1, %2};" : "=l"(r) : "f"(x), "f"(y));
    return r;
}
__device__ __forceinline__ void upk2(ull v, float &x, float &y) {
    asm("mov.b64 {%0, %1}, %2;" : "=f"(x), "=f"(y) : "l"(v));
}
__device__ __forceinline__ float sp_(float x) {
    return fmaxf(x, 0.f) + __logf(1.f + __expf(-fabsf(x)));
}
__device__ __forceinline__ float tanh_(float x) {
    float y;
    asm("tanh.approx.f32 %0, %1;" : "=f"(y) : "f"(x));
    return y;
}

// cubic Hermite derivative: dX = m0 + (diff-m0)*f*(4-3f)
__device__ __forceinline__ float spline_eval(const float* __restrict__ xrow, float t) {
    int idx = (int)t;
    idx = min(idx, L - 2);
    float f = t - (float)idx;
    const float* p = xrow + idx * C;
    float x0 = __ldg(p);
    float x1 = __ldg(p + C);
    float diff = x1 - x0;
    float m0 = diff;
    if (idx > 0) m0 = x0 - __ldg(p - C);
    return fmaf((diff - m0) * f, fmaf(-3.f, f, 4.f), m0);
}

// mm1 for NB own batches: sZb = &sZ[trio][b0][0] (row stride 32)
template<int NB>
__device__ __forceinline__ void mm1_run(const float* sZb, const ull* rw1, float rbf1,
                                        float* sH1b, int lane) {
    ull a1[NB];
#pragma unroll
    for (int k = 0; k < NB; k++) a1[k] = 0ull;
#pragma unroll
    for (int q = 0; q < 8; q++) {
#pragma unroll
        for (int k = 0; k < NB; k++) {
            ulonglong2 zq = *reinterpret_cast<const ulonglong2*>(sZb + k * 32 + 4 * q);
            a1[k] = ffma2(zq.x, rw1[2 * q], a1[k]);
            a1[k] = ffma2(zq.y, rw1[2 * q + 1], a1[k]);
        }
    }
#pragma unroll
    for (int k = 0; k < NB; k++) {
        float u, v; upk2(a1[k], u, v);
        sH1b[k * 32 + lane] = sp_(u + v + rbf1);
    }
}

// mm2 + tanh + einsum partial over all 7 batches (own NCH channels), batch-paired
template<int NCH>
__device__ __forceinline__ void mm2_all(const float (*sH1t)[32],    // [8][32]
                                        const float (*sDXs)[8],     // [8][8]
                                        const ull (*wreg)[16],      // [3][16]
                                        const float* b2, int cpos,
                                        float* sPw, int lane) {
#pragma unroll 1
    for (int bp = 0; bp < 3; bp++) {
        const int bs = 2 * bp;
        const float* h0 = &sH1t[bs][0];
        const float* h1 = &sH1t[bs + 1][0];
        ull a0[NCH], a1[NCH];
#pragma unroll
        for (int c = 0; c < NCH; c++) { a0[c] = 0ull; a1[c] = 0ull; }
#pragma unroll
        for (int q = 0; q < 8; q++) {
            ulonglong2 hq0 = *reinterpret_cast<const ulonglong2*>(h0 + 4 * q);
            ulonglong2 hq1 = *reinterpret_cast<const ulonglong2*>(h1 + 4 * q);
#pragma unroll
            for (int c = 0; c < NCH; c++) {
                a0[c] = ffma2(hq0.x, wreg[c][2 * q], a0[c]);
                a1[c] = ffma2(hq1.x, wreg[c][2 * q], a1[c]);
                a0[c] = ffma2(hq0.y, wreg[c][2 * q + 1], a0[c]);
                a1[c] = ffma2(hq1.y, wreg[c][2 * q + 1], a1[c]);
            }
        }
        float g0[NCH], g1[NCH];
#pragma unroll
        for (int c = 0; c < NCH; c++) {
            float u, v;
            upk2(a0[c], u, v); g0[c] = tanh_(u + v + b2[c]);
            upk2(a1[c], u, v); g1[c] = tanh_(u + v + b2[c]);
        }
        const float* d0 = &sDXs[bs][cpos];
        const float* d1 = &sDXs[bs + 1][cpos];
        ull e0 = ffma2(pk2(g0[0], g0[1]), *reinterpret_cast<const ull*>(d0), 0ull);
        ull e1 = ffma2(pk2(g1[0], g1[1]), *reinterpret_cast<const ull*>(d1), 0ull);
        float e0a, e0b, e1a, e1b;
        upk2(e0, e0a, e0b); upk2(e1, e1a, e1b);
        float r0 = e0a + e0b, r1 = e1a + e1b;
        if (NCH == 3) {
            r0 = fmaf(g0[2], d0[2], r0);
            r1 = fmaf(g1[2], d1[2], r1);
        }
        sPw[bs * 32 + lane] = r0;
        sPw[(bs + 1) * 32 + lane] = r1;
    }
    {   // singleton bs=6
        const int bs = 6;
        const float* h0 = &sH1t[bs][0];
        ull a0[NCH];
#pragma unroll
        for (int c = 0; c < NCH; c++) a0[c] = 0ull;
#pragma unroll
        for (int q = 0; q < 8; q++) {
            ulonglong2 hq0 = *reinterpret_cast<const ulonglong2*>(h0 + 4 * q);
#pragma unroll
            for (int c = 0; c < NCH; c++) {
                a0[c] = ffma2(hq0.x, wreg[c][2 * q], a0[c]);
                a0[c] = ffma2(hq0.y, wreg[c][2 * q + 1], a0[c]);
            }
        }
        float g0[NCH];
#pragma unroll
        for (int c = 0; c < NCH; c++) {
            float u, v; upk2(a0[c], u, v);
            g0[c] = tanh_(u + v + b2[c]);
        }
        const float* d0 = &sDXs[bs][cpos];
        ull e0 = ffma2(pk2(g0[0], g0[1]), *reinterpret_cast<const ull*>(d0), 0ull);
        float e0a, e0b; upk2(e0, e0a, e0b);
        float r0 = e0a + e0b;
        if (NCH == 3) r0 = fmaf(g0[2], d0[2], r0);
        sPw[bs * 32 + lane] = r0;
    }
}

__global__ __launch_bounds__(384, 1)
void cde_kernel(const float* __restrict__ X,      // (4096,64,7)
                const float* __restrict__ Winit,  // (32,7)
                const float* __restrict__ binit,  // (32)
                const float* __restrict__ Wf1,    // (32,32)
                const float* __restrict__ bf1,    // (32)
                const float* __restrict__ Wf2,    // (224,32)
                const float* __restrict__ bf2,    // (224)
                const float* __restrict__ Wo1,    // (16,32)
                const float* __restrict__ bo1,    // (16)
                const float* __restrict__ Wo2,    // (3,16)
                const float* __restrict__ bo2,    // (3)
                float* __restrict__ out)          // (4096,3)
{
    // 12 warps = 4 trios; each trio serves 7 batches (+ dummy slot 7).
    // Channel sets: {0,1,2} / {3,4} / {5,6}; dX storage pos: c<3 -> c, else c+1.
    __shared__ __align__(16) float sZ[4][8][32];        // 4 KB
    __shared__ __align__(16) float sH1[4][8][32];       // 4 KB
    __shared__ __align__(16) float sDX[4][3][8][8];     // 3 KB
    __shared__ __align__(16) float sPart[4][3][8][32];  // 12 KB

    const int tid  = threadIdx.x;
    const int w    = tid >> 5;
    const int lane = tid & 31;          // = h
    const int trio = w / 3;             // 0..3
    const int wt   = w - trio * 3;      // 0..2
    const int gbase = blockIdx.x * 28 + trio * 7;

    // ownership: batches 3/2/2 ; channels 2/2/3 (heavy-ch warp gets light batches)
    const int b0  = (wt == 0) ? 0 : (wt == 1) ? 3 : 5;
    const int nb  = (wt == 0) ? 3 : 2;
    const int nch = (wt == 2) ? 3 : 2;
    const int c0  = (wt == 0) ? 3 : (wt == 1) ? 5 : 0;   // first owned channel
    const int cpos = (wt == 0) ? 4 : (wt == 1) ? 6 : 0;  // its dX storage pos

    // ---- Wf2 owned channels, j-pair packed, in registers ----
    ull wreg[3][16];
    float b2[3];
#pragma unroll
    for (int cp = 0; cp < 3; cp++) {
        if (cp < nch) {
            int cg = c0 + cp;
            const float2* wp = reinterpret_cast<const float2*>(Wf2 + (lane * C + cg) * 32);
#pragma unroll
            for (int jp = 0; jp < 16; jp++) { float2 v = __ldg(wp + jp); wreg[cp][jp] = pk2(v.x, v.y); }
            b2[cp] = __ldg(bf2 + lane * C + cg);
        } else {
#pragma unroll
            for (int jp = 0; jp < 16; jp++) wreg[cp][jp] = 0ull;
            b2[cp] = 0.f;
        }
    }
    ull rw1[16];
    {
        const float2* p1 = reinterpret_cast<const float2*>(Wf1 + lane * 32);
#pragma unroll
        for (int jp = 0; jp < 16; jp++) { float2 v = __ldg(p1 + jp); rw1[jp] = pk2(v.x, v.y); }
    }
    const float rbf1 = __ldg(bf1 + lane);

    // spline mapping: wt0 -> slots 0-3, wt1 -> slots 4-6 (+7 dummy), wt2 none
    const int sl = wt * 4 + (lane >> 3);       // wt<2 only
    const int dc = lane & 7;
    const int dpos = (dc < 3) ? dc : dc + 1;   // storage position (dc<7)
    const bool spl = (wt < 2) && (dc < C);
    const int gsb = min(gbase + min(sl, 7), 4095);
    const float* xrow = X + (size_t)gsb * (L * C) + ((dc < C) ? dc : 0);

    // z0 for own batches (clamped)
    float z[3], zs[3], ksum[3];
#pragma unroll
    for (int k = 0; k < 3; k++) { z[k] = 0.f; ksum[k] = 0.f; }
    for (int k = 0; k < nb; k++) {
        int gb = min(gbase + b0 + k, 4095);
        float acc = __ldg(binit + lane);
        const float* xp = X + (size_t)gb * (L * C);
#pragma unroll
        for (int c = 0; c < C; c++) acc = fmaf(__ldg(xp + c), __ldg(Winit + lane * C + c), acc);
        z[k] = acc;
        zs[k] = acc;
        sZ[trio][b0 + k][lane] = acc;
    }

    // initial dX(t=0) -> slot 0
    if (spl && sl < 8) {
        float v = __ldg(xrow + C) - __ldg(xrow);
        sDX[trio][0][sl][dpos] = v;
    }
    __syncthreads();

    float t0 = 0.f;
#pragma unroll 1
    for (int i = 0; i < NSTEPS; i++, t0 += 0.5f) {
        // spline: t0+0.25 -> slot 2 ; t0+0.5 -> slot (i+1)&1
        if (spl) {
            float vb = spline_eval(xrow, t0 + 0.25f);
            float vc = spline_eval(xrow, t0 + 0.5f);
            sDX[trio][2][sl][dpos] = vb;
            sDX[trio][(i + 1) & 1][sl][dpos] = vc;
        }
        const int slotA = i & 1, slotC = (i + 1) & 1;

#pragma unroll 1
        for (int s = 0; s < 4; s++) {
            const int slot = (s == 0) ? slotA : ((s == 3) ? slotC : 2);

            // ---- mm1 (own batches; sZ rows are self-written) ----
            __syncwarp();
            if (nb == 3) mm1_run<3>(&sZ[trio][b0][0], rw1, rbf1, &sH1[trio][b0][0], lane);
            else         mm1_run<2>(&sZ[trio][b0][0], rw1, rbf1, &sH1[trio][b0][0], lane);
            asm volatile("bar.sync %0, 96;" :: "r"(trio + 1) : "memory");

            // ---- mm2 for all 7 batches (own channels) ----
            float* sPw = &sPart[trio][wt][0][0];
            if (nch == 3) mm2_all<3>(sH1[trio], sDX[trio][slot], wreg, b2, cpos, sPw, lane);
            else          mm2_all<2>(sH1[trio], sDX[trio][slot], wreg, b2, cpos, sPw, lane);
            asm volatile("bar.sync %0, 96;" :: "r"(trio + 1) : "memory");

            // ---- combine + RK4 (own batches) ----
            const float wk = (s == 1 || s == 2) ? 2.f : 1.f;
            const float an = (s < 2) ? 0.25f : 0.5f;
            for (int k = 0; k < nb; k++) {
                int bs = b0 + k;
                float kk = sPart[trio][0][bs][lane] + sPart[trio][1][bs][lane]
                         + sPart[trio][2][bs][lane];
                ksum[k] = fmaf(wk, kk, ksum[k]);
                float zsv;
                if (s < 3) {
                    zsv = fmaf(an, kk, z[k]);
                } else {
                    z[k] = fmaf(ksum[k], (1.f / 12.f), z[k]);  // h/6
                    ksum[k] = 0.f;
                    zsv = z[k];
                }
                zs[k] = zsv;
                sZ[trio][bs][lane] = zsv;
            }
        }
    }

    // drain trio before scratch reuse
    asm volatile("bar.sync %0, 96;" :: "r"(trio + 1) : "memory");

    // ---- output head (own batches) ----
    __syncwarp();
    float* so = &sPart[trio][wt][0][0];   // own-warp scratch (>= nb*32)
    if (lane < 16) {
        for (int k = 0; k < nb; k++) {
            float acc = __ldg(bo1 + lane);
#pragma unroll
            for (int hh = 0; hh < 32; hh++)
                acc = fmaf(sZ[trio][b0 + k][hh], __ldg(Wo1 + lane * 32 + hh), acc);
            so[k * 32 + lane] = sp_(acc);
        }
    }
    __syncwarp();
    if (lane < 3 * nb) {
        int k = lane / 3;
        int jo = lane - 3 * k;
        int gb = gbase + b0 + k;
        if (gb < 4096) {
            float acc = __ldg(bo2 + jo);
#pragma unroll
            for (int i2 = 0; i2 < 16; i2++)
                acc = fmaf(so[k * 32 + i2], __ldg(Wo2 + jo * 16 + i2), acc);
            out[(size_t)gb * 3 + jo] = acc;
        }
    }
}

extern "C" void kernel_launch(void* const* d_in, const int* in_sizes, int n_in,
                              void* d_out, int out_size) {
    const float* X     = (const float*)d_in[0];
    const float* Winit = (const float*)d_in[1];
    const float* binit = (const float*)d_in[2];
    const float* Wf1   = (const float*)d_in[3];
    const float* bf1   = (const float*)d_in[4];
    const float* Wf2   = (const float*)d_in[5];
    const float* bf2   = (const float*)d_in[6];
    const float* Wo1   = (const float*)d_in[7];
    const float* bo1   = (const float*)d_in[8];
    const float* Wo2   = (const float*)d_in[9];
    const float* bo2   = (const float*)d_in[10];
    float* out = (float*)d_out;

    // 147 CTAs x 384 thr (4 trios x 7 batches = 28/CTA) = 4116 slots >= 4096
    cde_kernel<<<NCTA, 384>>>(X, Winit, binit, Wf1, bf1, Wf2, bf2,
                              Wo1, bo1, Wo2, bo2, out);
}

// round 12
// speedup vs baseline: 1.2195x; 1.1910x over previous
#include <cuda_runtime.h>

#define L 64
#define C 7
#define NSTEPS 126   // (L-1)*K, K=2, h=0.5
#define NBPAIR 7     // batches per warp-pair
#define NCTA 293     // 2 pairs per CTA

typedef unsigned long long ull;

__device__ __forceinline__ ull ffma2(ull a, ull b, ull c) {
    ull d;
    asm("fma.rn.f32x2 %0, %1, %2, %3;" : "=l"(d) : "l"(a), "l"(b), "l"(c));
    return d;
}
__device__ __forceinline__ ull pk2(float x, float y) {
    ull r;
    asm("mov.b64 %0, {%1, %2};" : "=l"(r) : "f"(x), "f"(y));
    return r;
}
__device__ __forceinline__ void upk2(ull v, float &x, float &y) {
    asm("mov.b64 {%0, %1}, %2;" : "=f"(x), "=f"(y) : "l"(v));
}
__device__ __forceinline__ float sp_(float x) {
    return fmaxf(x, 0.f) + __logf(1.f + __expf(-fabsf(x)));
}
__device__ __forceinline__ float tanh_(float x) {
    float y;
    asm("tanh.approx.f32 %0, %1;" : "=f"(y) : "f"(x));
    return y;
}

#define BAR_ARRIVE(id) asm volatile("bar.arrive %0, 64;" :: "r"(id) : "memory")
#define BAR_SYNCN(id)  asm volatile("bar.sync %0, 64;"   :: "r"(id) : "memory")

// cubic Hermite derivative: dX = m0 + (diff-m0)*f*(4-3f)
__device__ __forceinline__ float spline_eval(const float* __restrict__ xrow, float t) {
    int idx = (int)t;
    idx = min(idx, L - 2);
    float f = t - (float)idx;
    const float* p = xrow + idx * C;
    float x0 = __ldg(p);
    float x1 = __ldg(p + C);
    float diff = x1 - x0;
    float m0 = diff;
    if (idx > 0) m0 = x0 - __ldg(p - C);
    return fmaf((diff - m0) * f, fmaf(-3.f, f, 4.f), m0);
}

// mm1 for NB batches starting at row sZb (stride 32), h1 -> sH1b
template<int NB>
__device__ __forceinline__ void mm1_run(const float* sZb, const ull* rw1, float rbf1,
                                        float* sH1b, int lane) {
    ull a1[NB];
#pragma unroll
    for (int k = 0; k < NB; k++) a1[k] = 0ull;
#pragma unroll
    for (int q = 0; q < 8; q++) {
#pragma unroll
        for (int k = 0; k < NB; k++) {
            ulonglong2 zq = *reinterpret_cast<const ulonglong2*>(sZb + k * 32 + 4 * q);
            a1[k] = ffma2(zq.x, rw1[2 * q], a1[k]);
            a1[k] = ffma2(zq.y, rw1[2 * q + 1], a1[k]);
        }
    }
#pragma unroll
    for (int k = 0; k < NB; k++) {
        float u, v; upk2(a1[k], u, v);
        sH1b[k * 32 + lane] = sp_(u + v + rbf1);
    }
}

// mm2 + tanh + einsum partial for TWO batches (NCH own channels)
template<int NCH>
__device__ __forceinline__ void mm2_two(const float* h0, const float* h1,
                                        const float* d0, const float* d1,
                                        const ull (*wreg)[16], const float* b2,
                                        float& r0, float& r1) {
    ull a0[NCH], a1[NCH];
#pragma unroll
    for (int c = 0; c < NCH; c++) { a0[c] = 0ull; a1[c] = 0ull; }
#pragma unroll
    for (int q = 0; q < 8; q++) {
        ulonglong2 hq0 = *reinterpret_cast<const ulonglong2*>(h0 + 4 * q);
        ulonglong2 hq1 = *reinterpret_cast<const ulonglong2*>(h1 + 4 * q);
#pragma unroll
        for (int c = 0; c < NCH; c++) {
            a0[c] = ffma2(hq0.x, wreg[c][2 * q], a0[c]);
            a1[c] = ffma2(hq1.x, wreg[c][2 * q], a1[c]);
            a0[c] = ffma2(hq0.y, wreg[c][2 * q + 1], a0[c]);
            a1[c] = ffma2(hq1.y, wreg[c][2 * q + 1], a1[c]);
        }
    }
    float g0[NCH], g1[NCH];
#pragma unroll
    for (int c = 0; c < NCH; c++) {
        float u, v;
        upk2(a0[c], u, v); g0[c] = tanh_(u + v + b2[c]);
        upk2(a1[c], u, v); g1[c] = tanh_(u + v + b2[c]);
    }
    ull e0 = ffma2(pk2(g0[0], g0[1]), *reinterpret_cast<const ull*>(d0), 0ull);
    ull e1 = ffma2(pk2(g1[0], g1[1]), *reinterpret_cast<const ull*>(d1), 0ull);
    if (NCH == 4) {
        e0 = ffma2(pk2(g0[2], g0[3]), *reinterpret_cast<const ull*>(d0 + 2), e0);
        e1 = ffma2(pk2(g1[2], g1[3]), *reinterpret_cast<const ull*>(d1 + 2), e1);
    }
    float a, b;
    upk2(e0, a, b); r0 = a + b;
    upk2(e1, a, b); r1 = a + b;
    if (NCH == 3) {
        r0 = fmaf(g0[2], d0[2], r0);
        r1 = fmaf(g1[2], d1[2], r1);
    }
}

// single-batch variant
template<int NCH>
__device__ __forceinline__ float mm2_one(const float* h0, const float* d0,
                                         const ull (*wreg)[16], const float* b2) {
    ull a0[NCH];
#pragma unroll
    for (int c = 0; c < NCH; c++) a0[c] = 0ull;
#pragma unroll
    for (int q = 0; q < 8; q++) {
        ulonglong2 hq0 = *reinterpret_cast<const ulonglong2*>(h0 + 4 * q);
#pragma unroll
        for (int c = 0; c < NCH; c++) {
            a0[c] = ffma2(hq0.x, wreg[c][2 * q], a0[c]);
            a0[c] = ffma2(hq0.y, wreg[c][2 * q + 1], a0[c]);
        }
    }
    float g0[NCH];
#pragma unroll
    for (int c = 0; c < NCH; c++) {
        float u, v; upk2(a0[c], u, v);
        g0[c] = tanh_(u + v + b2[c]);
    }
    ull e0 = ffma2(pk2(g0[0], g0[1]), *reinterpret_cast<const ull*>(d0), 0ull);
    if (NCH == 4) e0 = ffma2(pk2(g0[2], g0[3]), *reinterpret_cast<const ull*>(d0 + 2), e0);
    float a, b; upk2(e0, a, b);
    float r = a + b;
    if (NCH == 3) r = fmaf(g0[2], d0[2], r);
    return r;
}

__global__ __launch_bounds__(128, 2)
void cde_kernel(const float* __restrict__ X,      // (4096,64,7)
                const float* __restrict__ Winit,  // (32,7)
                const float* __restrict__ binit,  // (32)
                const float* __restrict__ Wf1,    // (32,32)
                const float* __restrict__ bf1,    // (32)
                const float* __restrict__ Wf2,    // (224,32)
                const float* __restrict__ bf2,    // (224)
                const float* __restrict__ Wo1,    // (16,32)
                const float* __restrict__ bo1,    // (16)
                const float* __restrict__ Wo2,    // (3,16)
                const float* __restrict__ bo2,    // (3)
                float* __restrict__ out)          // (4096,3)
{
    // 4 warps = 2 pairs; pair serves 7 batches.
    // Warp A (isB=0): channels {0..3} (NCH=4), batches {0,1}   (nb=2)
    // Warp B (isB=1): channels {4,5,6} (NCH=3), batches {2..6} (nb=5)
    __shared__ __align__(16) float sZ[2][8][32];     // zs per batch slot (owner-written)
    __shared__ __align__(16) float sH1[2][8][32];    // h1 (owner-written)
    __shared__ __align__(16) float sDX[2][3][8][8];  // spline values
    __shared__ __align__(16) float sPart[4][8][32];  // einsum partials per warp

    const int tid  = threadIdx.x;
    const int w    = tid >> 5;
    const int lane = tid & 31;          // = h
    const int pair = w >> 1;
    const int isB  = w & 1;
    const int partner = w ^ 1;
    const int gpair = blockIdx.x * 2 + pair;
    const int pairbase = gpair * NBPAIR;

    const int b0  = isB ? 2 : 0;
    const int nb  = isB ? 5 : 2;
    const int c0  = isB ? 4 : 0;        // first owned channel
    const int nch = isB ? 3 : 4;
    // named barriers: own h1 = 1+w_in_cta, own p2 = 5+w_in_cta
    const int bh_own = 1 + w, bh_par = 1 + partner;
    const int bp_own = 5 + w, bp_par = 5 + partner;

    // ---- Wf2 owned channels, j-pair packed, in registers ----
    ull wreg[4][16];
    float b2[4];
#pragma unroll
    for (int cp = 0; cp < 4; cp++) {
        if (cp < nch) {
            int cg = c0 + cp;
            const float2* wp = reinterpret_cast<const float2*>(Wf2 + (lane * C + cg) * 32);
#pragma unroll
            for (int jp = 0; jp < 16; jp++) { float2 v = __ldg(wp + jp); wreg[cp][jp] = pk2(v.x, v.y); }
            b2[cp] = __ldg(bf2 + lane * C + cg);
        } else {
#pragma unroll
            for (int jp = 0; jp < 16; jp++) wreg[cp][jp] = 0ull;
            b2[cp] = 0.f;
        }
    }
    ull rw1[16];
    {
        const float2* p1 = reinterpret_cast<const float2*>(Wf1 + lane * 32);
#pragma unroll
        for (int jp = 0; jp < 16; jp++) { float2 v = __ldg(p1 + jp); rw1[jp] = pk2(v.x, v.y); }
    }
    const float rbf1 = __ldg(bf1 + lane);

    // spline mapping: A writes dX rows 0-3, B rows 4-7 (row 7 dummy)
    const int db = lane >> 3;
    const int dc = lane & 7;
    const int srow = isB * 4 + db;
    const int sbatch = min(pairbase + srow, 4095);
    const float* xrow = X + (size_t)sbatch * (L * C) + ((dc < C) ? dc : 0);

    // z0 for own batches
    float z[5], ksum[5];
#pragma unroll
    for (int k = 0; k < 5; k++) { z[k] = 0.f; ksum[k] = 0.f; }
    for (int k = 0; k < nb; k++) {
        int gb = min(pairbase + b0 + k, 4095);
        float acc = __ldg(binit + lane);
        const float* xp = X + (size_t)gb * (L * C);
#pragma unroll
        for (int c = 0; c < C; c++) acc = fmaf(__ldg(xp + c), __ldg(Winit + lane * C + c), acc);
        z[k] = acc;
        sZ[pair][b0 + k][lane] = acc;
    }

    // initial dX(t=0) -> slot 0
    {
        float v = 0.f;
        if (dc < C) v = __ldg(xrow + C) - __ldg(xrow);
        sDX[pair][0][srow][dc] = v;
    }
    __syncthreads();

    float t0 = 0.f;
#pragma unroll 1
    for (int i = 0; i < NSTEPS; i++, t0 += 0.5f) {
        // spline: t0+0.25 -> slot 2 ; t0+0.5 -> slot (i+1)&1
        {
            float vb = 0.f, vc = 0.f;
            if (dc < C) {
                vb = spline_eval(xrow, t0 + 0.25f);
                vc = spline_eval(xrow, t0 + 0.5f);
            }
            sDX[pair][2][srow][dc] = vb;
            sDX[pair][(i + 1) & 1][srow][dc] = vc;
        }
        const int slotA = i & 1, slotC = (i + 1) & 1;

#pragma unroll 1
        for (int s = 0; s < 4; s++) {
            const int slot = (s == 0) ? slotA : ((s == 3) ? slotC : 2);
            const float* dxs = &sDX[pair][slot][0][0];   // rows of 8
            float* sPw = &sPart[w][0][0];
            const float* h1t = &sH1[pair][0][0];

            // ---- 1: mm1 own batches ----
            __syncwarp();
            if (isB) mm1_run<5>(&sZ[pair][2][0], rw1, rbf1, &sH1[pair][2][0], lane);
            else     mm1_run<2>(&sZ[pair][0][0], rw1, rbf1, &sH1[pair][0][0], lane);
            __syncwarp();
            // ---- 2: my h1 is ready for partner ----
            BAR_ARRIVE(bh_par);

            // ---- 3: mm2 on OWN batches (own h1 only) ----
            if (isB) {
                float r0, r1;
                mm2_two<3>(h1t + 2 * 32, h1t + 3 * 32, dxs + 2 * 8 + 4, dxs + 3 * 8 + 4, wreg, b2, r0, r1);
                sPw[2 * 32 + lane] = r0; sPw[3 * 32 + lane] = r1;
                mm2_two<3>(h1t + 4 * 32, h1t + 5 * 32, dxs + 4 * 8 + 4, dxs + 5 * 8 + 4, wreg, b2, r0, r1);
                sPw[4 * 32 + lane] = r0; sPw[5 * 32 + lane] = r1;
                sPw[6 * 32 + lane] = mm2_one<3>(h1t + 6 * 32, dxs + 6 * 8 + 4, wreg, b2);
            } else {
                float r0, r1;
                mm2_two<4>(h1t, h1t + 32, dxs, dxs + 8, wreg, b2, r0, r1);
                sPw[lane] = r0; sPw[32 + lane] = r1;
            }

            // ---- 4: wait for partner h1 ----
            BAR_SYNCN(bh_own);

            // ---- 5: mm2 on PARTNER batches ----
            if (isB) {
                float r0, r1;
                mm2_two<3>(h1t, h1t + 32, dxs + 4, dxs + 8 + 4, wreg, b2, r0, r1);
                sPw[lane] = r0; sPw[32 + lane] = r1;
            } else {
                float r0, r1;
                mm2_two<4>(h1t + 2 * 32, h1t + 3 * 32, dxs + 2 * 8, dxs + 3 * 8, wreg, b2, r0, r1);
                sPw[2 * 32 + lane] = r0; sPw[3 * 32 + lane] = r1;
                mm2_two<4>(h1t + 4 * 32, h1t + 5 * 32, dxs + 4 * 8, dxs + 5 * 8, wreg, b2, r0, r1);
                sPw[4 * 32 + lane] = r0; sPw[5 * 32 + lane] = r1;
                sPw[6 * 32 + lane] = mm2_one<4>(h1t + 6 * 32, dxs + 6 * 8, wreg, b2);
            }
            // ---- 6: my partials for partner's combine are ready ----
            BAR_ARRIVE(bp_par);
            // ---- 7: wait for partner's partials for MY batches ----
            BAR_SYNCN(bp_own);

            // ---- 8: combine + RK4 (own batches) ----
            const float wk = (s == 1 || s == 2) ? 2.f : 1.f;
            const float an = (s < 2) ? 0.25f : 0.5f;
            const float* pA = &sPart[2 * pair][0][0];
            const float* pB = &sPart[2 * pair + 1][0][0];
            for (int k = 0; k < nb; k++) {
                int bs = b0 + k;
                float kk = pA[bs * 32 + lane] + pB[bs * 32 + lane];
                ksum[k] = fmaf(wk, kk, ksum[k]);
                float zsv;
                if (s < 3) {
                    zsv = fmaf(an, kk, z[k]);
                } else {
                    z[k] = fmaf(ksum[k], (1.f / 12.f), z[k]);  // h/6
                    ksum[k] = 0.f;
                    zsv = z[k];
                }
                sZ[pair][bs][lane] = zsv;
            }
        }
    }

    __syncthreads();   // drain before scratch reuse

    // ---- output head (own batches) ----
    __syncwarp();
    float* so = &sPart[w][0][0];   // own-warp scratch (nb*32 <= 256)
    if (lane < 16) {
        for (int k = 0; k < nb; k++) {
            float acc = __ldg(bo1 + lane);
#pragma unroll
            for (int hh = 0; hh < 32; hh++)
                acc = fmaf(sZ[pair][b0 + k][hh], __ldg(Wo1 + lane * 32 + hh), acc);
            so[k * 32 + lane] = sp_(acc);
        }
    }
    __syncwarp();
    if (lane < 3 * nb) {
        int k = lane / 3;
        int jo = lane - 3 * k;
        int gb = pairbase + b0 + k;
        if (gb < 4096) {
            float acc = __ldg(bo2 + jo);
#pragma unroll
            for (int i2 = 0; i2 < 16; i2++)
                acc = fmaf(so[k * 32 + i2], __ldg(Wo2 + jo * 16 + i2), acc);
            out[(size_t)gb * 3 + jo] = acc;
        }
    }
}

extern "C" void kernel_launch(void* const* d_in, const int* in_sizes, int n_in,
                              void* d_out, int out_size) {
    const float* X     = (const float*)d_in[0];
    const float* Winit = (const float*)d_in[1];
    const float* binit = (const float*)d_in[2];
    const float* Wf1   = (const float*)d_in[3];
    const float* bf1   = (const float*)d_in[4];
    const float* Wf2   = (const float*)d_in[5];
    const float* bf2   = (const float*)d_in[6];
    const float* Wo1   = (const float*)d_in[7];
    const float* bo1   = (const float*)d_in[8];
    const float* Wo2   = (const float*)d_in[9];
    const float* bo2   = (const float*)d_in[10];
    float* out = (float*)d_out;

    // 293 CTAs x 128 thr: 2 pairs/CTA x 7 batches = 4102 slots >= 4096 (tail guarded)
    cde_kernel<<<NCTA, 128>>>(X, Winit, binit, Wf1, bf1, Wf2, bf2,
                              Wo1, bo1, Wo2, bo2, out);
}

// round 13
// speedup vs baseline: 1.2351x; 1.0128x over previous
#include <cuda_runtime.h>

#define L 64
#define C 7
#define NSTEPS 126   // (L-1)*K, K=2, h=0.5
#define NBPAIR 7     // batches per warp-pair
#define NCTA 293     // 2 pairs per CTA

typedef unsigned long long ull;

__device__ __forceinline__ ull ffma2(ull a, ull b, ull c) {
    ull d;
    asm("fma.rn.f32x2 %0, %1, %2, %3;" : "=l"(d) : "l"(a), "l"(b), "l"(c));
    return d;
}
__device__ __forceinline__ ull pk2(float x, float y) {
    ull r;
    asm("mov.b64 %0, {%1, %2};" : "=l"(r) : "f"(x), "f"(y));
    return r;
}
__device__ __forceinline__ void upk2(ull v, float &x, float &y) {
    asm("mov.b64 {%0, %1}, %2;" : "=f"(x), "=f"(y) : "l"(v));
}
__device__ __forceinline__ float sp_(float x) {
    return fmaxf(x, 0.f) + __logf(1.f + __expf(-fabsf(x)));
}
__device__ __forceinline__ float tanh_(float x) {
    float y;
    asm("tanh.approx.f32 %0, %1;" : "=f"(y) : "f"(x));
    return y;
}

#define BAR_ARRIVE(id) asm volatile("bar.arrive %0, 64;" :: "r"(id) : "memory")
#define BAR_SYNCN(id)  asm volatile("bar.sync %0, 64;"   :: "r"(id) : "memory")

// mm1 for NB batches starting at row sZb (stride 32), h1 -> sH1b
template<int NB>
__device__ __forceinline__ void mm1_run(const float* sZb, const ull* rw1, float rbf1,
                                        float* sH1b, int lane) {
    ull a1[NB];
#pragma unroll
    for (int k = 0; k < NB; k++) a1[k] = 0ull;
#pragma unroll
    for (int q = 0; q < 8; q++) {
#pragma unroll
        for (int k = 0; k < NB; k++) {
            ulonglong2 zq = *reinterpret_cast<const ulonglong2*>(sZb + k * 32 + 4 * q);
            a1[k] = ffma2(zq.x, rw1[2 * q], a1[k]);
            a1[k] = ffma2(zq.y, rw1[2 * q + 1], a1[k]);
        }
    }
#pragma unroll
    for (int k = 0; k < NB; k++) {
        float u, v; upk2(a1[k], u, v);
        sH1b[k * 32 + lane] = sp_(u + v + rbf1);
    }
}

// mm2 + tanh + einsum partial for TWO batches (NCH own channels)
template<int NCH>
__device__ __forceinline__ void mm2_two(const float* h0, const float* h1,
                                        const float* d0, const float* d1,
                                        const ull (*wreg)[16], const float* b2,
                                        float& r0, float& r1) {
    ull a0[NCH], a1[NCH];
#pragma unroll
    for (int c = 0; c < NCH; c++) { a0[c] = 0ull; a1[c] = 0ull; }
#pragma unroll
    for (int q = 0; q < 8; q++) {
        ulonglong2 hq0 = *reinterpret_cast<const ulonglong2*>(h0 + 4 * q);
        ulonglong2 hq1 = *reinterpret_cast<const ulonglong2*>(h1 + 4 * q);
#pragma unroll
        for (int c = 0; c < NCH; c++) {
            a0[c] = ffma2(hq0.x, wreg[c][2 * q], a0[c]);
            a1[c] = ffma2(hq1.x, wreg[c][2 * q], a1[c]);
            a0[c] = ffma2(hq0.y, wreg[c][2 * q + 1], a0[c]);
            a1[c] = ffma2(hq1.y, wreg[c][2 * q + 1], a1[c]);
        }
    }
    float g0[NCH], g1[NCH];
#pragma unroll
    for (int c = 0; c < NCH; c++) {
        float u, v;
        upk2(a0[c], u, v); g0[c] = tanh_(u + v + b2[c]);
        upk2(a1[c], u, v); g1[c] = tanh_(u + v + b2[c]);
    }
    ull e0 = ffma2(pk2(g0[0], g0[1]), *reinterpret_cast<const ull*>(d0), 0ull);
    ull e1 = ffma2(pk2(g1[0], g1[1]), *reinterpret_cast<const ull*>(d1), 0ull);
    if (NCH == 4) {
        e0 = ffma2(pk2(g0[2], g0[3]), *reinterpret_cast<const ull*>(d0 + 2), e0);
        e1 = ffma2(pk2(g1[2], g1[3]), *reinterpret_cast<const ull*>(d1 + 2), e1);
    }
    float a, b;
    upk2(e0, a, b); r0 = a + b;
    upk2(e1, a, b); r1 = a + b;
    if (NCH == 3) {
        r0 = fmaf(g0[2], d0[2], r0);
        r1 = fmaf(g1[2], d1[2], r1);
    }
}

// single-batch variant
template<int NCH>
__device__ __forceinline__ float mm2_one(const float* h0, const float* d0,
                                         const ull (*wreg)[16], const float* b2) {
    ull a0[NCH];
#pragma unroll
    for (int c = 0; c < NCH; c++) a0[c] = 0ull;
#pragma unroll
    for (int q = 0; q < 8; q++) {
        ulonglong2 hq0 = *reinterpret_cast<const ulonglong2*>(h0 + 4 * q);
#pragma unroll
        for (int c = 0; c < NCH; c++) {
            a0[c] = ffma2(hq0.x, wreg[c][2 * q], a0[c]);
            a0[c] = ffma2(hq0.y, wreg[c][2 * q + 1], a0[c]);
        }
    }
    float g0[NCH];
#pragma unroll
    for (int c = 0; c < NCH; c++) {
        float u, v; upk2(a0[c], u, v);
        g0[c] = tanh_(u + v + b2[c]);
    }
    ull e0 = ffma2(pk2(g0[0], g0[1]), *reinterpret_cast<const ull*>(d0), 0ull);
    if (NCH == 4) e0 = ffma2(pk2(g0[2], g0[3]), *reinterpret_cast<const ull*>(d0 + 2), e0);
    float a, b; upk2(e0, a, b);
    float r = a + b;
    if (NCH == 3) r = fmaf(g0[2], d0[2], r);
    return r;
}

__global__ __launch_bounds__(128, 2)
void cde_kernel(const float* __restrict__ X,      // (4096,64,7)
                const float* __restrict__ Winit,  // (32,7)
                const float* __restrict__ binit,  // (32)
                const float* __restrict__ Wf1,    // (32,32)
                const float* __restrict__ bf1,    // (32)
                const float* __restrict__ Wf2,    // (224,32)
                const float* __restrict__ bf2,    // (224)
                const float* __restrict__ Wo1,    // (16,32)
                const float* __restrict__ bo1,    // (16)
                const float* __restrict__ Wo2,    // (3,16)
                const float* __restrict__ bo2,    // (3)
                float* __restrict__ out)          // (4096,3)
{
    // 4 warps = 2 pairs; pair serves 7 batches.
    // Warp A (isB=0): channels {0..3} (NCH=4), batches {0,1}   (nb=2)
    // Warp B (isB=1): channels {4,5,6} (NCH=3), batches {2..6} (nb=5)
    __shared__ __align__(16) float sZ[2][8][32];     // zs per batch slot (owner-written)
    __shared__ __align__(16) float sH1[2][8][32];    // h1 (owner-written)
    __shared__ __align__(16) float sDX[2][3][8][8];  // spline values
    __shared__ __align__(16) float sPart[4][8][32];  // einsum partials per warp

    const int tid  = threadIdx.x;
    const int w    = tid >> 5;
    const int lane = tid & 31;          // = h
    const int pair = w >> 1;
    const int isB  = w & 1;
    const int gpair = blockIdx.x * 2 + pair;
    const int pairbase = gpair * NBPAIR;

    const int b0  = isB ? 2 : 0;
    const int nb  = isB ? 5 : 2;
    const int c0  = isB ? 4 : 0;        // first owned channel
    const int nch = isB ? 3 : 4;
    // named barriers (count 64 = 32 arrive + 32 sync):
    //  b1: B h1 chunk {2,3,4} -> A     b2: B h1 chunk {5,6} -> A
    //  b3: A h1 {0,1} -> B
    //  b4: B partials -> A             b5: A partials -> B
    const int base = pair * 5;

    // ---- Wf2 owned channels, j-pair packed, in registers ----
    ull wreg[4][16];
    float b2[4];
#pragma unroll
    for (int cp = 0; cp < 4; cp++) {
        if (cp < nch) {
            int cg = c0 + cp;
            const float2* wp = reinterpret_cast<const float2*>(Wf2 + (lane * C + cg) * 32);
#pragma unroll
            for (int jp = 0; jp < 16; jp++) { float2 v = __ldg(wp + jp); wreg[cp][jp] = pk2(v.x, v.y); }
            b2[cp] = __ldg(bf2 + lane * C + cg);
        } else {
#pragma unroll
            for (int jp = 0; jp < 16; jp++) wreg[cp][jp] = 0ull;
            b2[cp] = 0.f;
        }
    }
    ull rw1[16];
    {
        const float2* p1 = reinterpret_cast<const float2*>(Wf1 + lane * 32);
#pragma unroll
        for (int jp = 0; jp < 16; jp++) { float2 v = __ldg(p1 + jp); rw1[jp] = pk2(v.x, v.y); }
    }
    const float rbf1 = __ldg(bf1 + lane);

    // spline mapping: A writes dX rows 0-3, B rows 4-7 (row 7 dummy)
    const int db = lane >> 3;
    const int dc = lane & 7;
    const int srow = isB * 4 + db;
    const int sbatch = min(pairbase + srow, 4095);
    const float* xrow = X + (size_t)sbatch * (L * C) + ((dc < C) ? dc : 0);

    // z0 for own batches
    float z[5], ksum[5];
#pragma unroll
    for (int k = 0; k < 5; k++) { z[k] = 0.f; ksum[k] = 0.f; }
    for (int k = 0; k < nb; k++) {
        int gb = min(pairbase + b0 + k, 4095);
        float acc = __ldg(binit + lane);
        const float* xp = X + (size_t)gb * (L * C);
#pragma unroll
        for (int c = 0; c < C; c++) acc = fmaf(__ldg(xp + c), __ldg(Winit + lane * C + c), acc);
        z[k] = acc;
        sZ[pair][b0 + k][lane] = acc;
    }

    // initial dX(t=0) -> slot 0  (idx=0,f=0 -> diff)
    {
        float v = 0.f;
        if (dc < C) v = __ldg(xrow + C) - __ldg(xrow);
        sDX[pair][0][srow][dc] = v;
    }
    __syncthreads();

#pragma unroll 1
    for (int i = 0; i < NSTEPS; i++) {
        // ---- spline (shared 3-load stencil; m1 == diff algebraically) ----
        // t0 = i/2; m = i>>1; even i: f=0.25,0.5 on segment m; odd i: f=0.75 and vc=diff
        {
            const int m = i >> 1;
            const float* p = xrow + m * C;
            float xm1 = 0.f, x0 = 0.f, x1 = 0.f;
            if (dc < C) {
                x0 = __ldg(p);
                x1 = __ldg(p + C);
                if (m > 0) xm1 = __ldg(p - C);
            }
            float diff = x1 - x0;
            float m0 = (m > 0) ? (x0 - xm1) : diff;
            float dm = diff - m0;
            // eval(f) = m0 + dm * f * (4 - 3f)
            float fac = (i & 1) ? 1.3125f : 0.8125f;      // f*(4-3f) at f=0.75 / 0.25
            float vb = fmaf(dm, fac, m0);
            float vc = (i & 1) ? diff : fmaf(dm, 1.25f, m0);  // f=0.5 -> 1.25
            sDX[pair][2][srow][dc] = vb;
            sDX[pair][(i + 1) & 1][srow][dc] = vc;
        }
        const int slotA = i & 1, slotC = (i + 1) & 1;

#pragma unroll 1
        for (int s = 0; s < 4; s++) {
            const int slot = (s == 0) ? slotA : ((s == 3) ? slotC : 2);
            const float* dxs = &sDX[pair][slot][0][0];   // rows of 8
            float* sPw = &sPart[w][0][0];
            const float* h1t = &sH1[pair][0][0];

            __syncwarp();
            if (!isB) {
                // ---- A: mm1 {0,1} -> publish -> mm2 own -> consume B chunks ----
                mm1_run<2>(&sZ[pair][0][0], rw1, rbf1, &sH1[pair][0][0], lane);
                BAR_ARRIVE(base + 3);
                {
                    float r0, r1;
                    mm2_two<4>(h1t, h1t + 32, dxs, dxs + 8, wreg, b2, r0, r1);
                    sPw[lane] = r0; sPw[32 + lane] = r1;
                }
                BAR_SYNCN(base + 1);          // B h1 {2,3,4} ready
                {
                    float r0, r1;
                    mm2_two<4>(h1t + 64, h1t + 96, dxs + 16, dxs + 24, wreg, b2, r0, r1);
                    sPw[64 + lane] = r0; sPw[96 + lane] = r1;
                    sPw[128 + lane] = mm2_one<4>(h1t + 128, dxs + 32, wreg, b2);
                }
                BAR_SYNCN(base + 2);          // B h1 {5,6} ready
                {
                    float r0, r1;
                    mm2_two<4>(h1t + 160, h1t + 192, dxs + 40, dxs + 48, wreg, b2, r0, r1);
                    sPw[160 + lane] = r0; sPw[192 + lane] = r1;
                }
                BAR_ARRIVE(base + 5);         // my partials -> B
                BAR_SYNCN(base + 4);          // B partials -> me
            } else {
                // ---- B: mm1 chunk {2,3,4} -> publish; chunk {5,6} -> publish ----
                mm1_run<3>(&sZ[pair][2][0], rw1, rbf1, &sH1[pair][2][0], lane);
                BAR_ARRIVE(base + 1);
                mm1_run<2>(&sZ[pair][5][0], rw1, rbf1, &sH1[pair][5][0], lane);
                BAR_ARRIVE(base + 2);
                {   // mm2 own batches {2..6}, channels {4,5,6}
                    float r0, r1;
                    mm2_two<3>(h1t + 64, h1t + 96, dxs + 16 + 4, dxs + 24 + 4, wreg, b2, r0, r1);
                    sPw[64 + lane] = r0; sPw[96 + lane] = r1;
                    mm2_two<3>(h1t + 128, h1t + 160, dxs + 32 + 4, dxs + 40 + 4, wreg, b2, r0, r1);
                    sPw[128 + lane] = r0; sPw[160 + lane] = r1;
                    sPw[192 + lane] = mm2_one<3>(h1t + 192, dxs + 48 + 4, wreg, b2);
                }
                BAR_SYNCN(base + 3);          // A h1 {0,1} ready
                {
                    float r0, r1;
                    mm2_two<3>(h1t, h1t + 32, dxs + 4, dxs + 8 + 4, wreg, b2, r0, r1);
                    sPw[lane] = r0; sPw[32 + lane] = r1;
                }
                BAR_ARRIVE(base + 4);         // my partials -> A
                BAR_SYNCN(base + 5);          // A partials -> me
            }

            // ---- combine + RK4 (own batches) ----
            const float wk = (s == 1 || s == 2) ? 2.f : 1.f;
            const float an = (s < 2) ? 0.25f : 0.5f;
            const float* pA = &sPart[2 * pair][0][0];
            const float* pB = &sPart[2 * pair + 1][0][0];
            for (int k = 0; k < nb; k++) {
                int bs = b0 + k;
                float kk = pA[bs * 32 + lane] + pB[bs * 32 + lane];
                ksum[k] = fmaf(wk, kk, ksum[k]);
                float zsv;
                if (s < 3) {
                    zsv = fmaf(an, kk, z[k]);
                } else {
                    z[k] = fmaf(ksum[k], (1.f / 12.f), z[k]);  // h/6
                    ksum[k] = 0.f;
                    zsv = z[k];
                }
                sZ[pair][bs][lane] = zsv;
            }
        }
    }

    __syncthreads();   // drain before scratch reuse

    // ---- output head (own batches) ----
    __syncwarp();
    float* so = &sPart[w][0][0];   // own-warp scratch (nb*32 <= 256)
    if (lane < 16) {
        for (int k = 0; k < nb; k++) {
            float acc = __ldg(bo1 + lane);
#pragma unroll
            for (int hh = 0; hh < 32; hh++)
                acc = fmaf(sZ[pair][b0 + k][hh], __ldg(Wo1 + lane * 32 + hh), acc);
            so[k * 32 + lane] = sp_(acc);
        }
    }
    __syncwarp();
    if (lane < 3 * nb) {
        int k = lane / 3;
        int jo = lane - 3 * k;
        int gb = pairbase + b0 + k;
        if (gb < 4096) {
            float acc = __ldg(bo2 + jo);
#pragma unroll
            for (int i2 = 0; i2 < 16; i2++)
                acc = fmaf(so[k * 32 + i2], __ldg(Wo2 + jo * 16 + i2), acc);
            out[(size_t)gb * 3 + jo] = acc;
        }
    }
}

extern "C" void kernel_launch(void* const* d_in, const int* in_sizes, int n_in,
                              void* d_out, int out_size) {
    const float* X     = (const float*)d_in[0];
    const float* Winit = (const float*)d_in[1];
    const float* binit = (const float*)d_in[2];
    const float* Wf1   = (const float*)d_in[3];
    const float* bf1   = (const float*)d_in[4];
    const float* Wf2   = (const float*)d_in[5];
    const float* bf2   = (const float*)d_in[6];
    const float* Wo1   = (const float*)d_in[7];
    const float* bo1   = (const float*)d_in[8];
    const float* Wo2   = (const float*)d_in[9];
    const float* bo2   = (const float*)d_in[10];
    float* out = (float*)d_out;

    // 293 CTAs x 128 thr: 2 pairs/CTA x 7 batches = 4102 slots >= 4096 (tail guarded)
    cde_kernel<<<NCTA, 128>>>(X, Winit, binit, Wf1, bf1, Wf2, bf2,
                              Wo1, bo1, Wo2, bo2, out);
}

// round 14
// speedup vs baseline: 1.2360x; 1.0007x over previous
#include <cuda_runtime.h>

#define L 64
#define C 7
#define NSTEPS 126   // (L-1)*K, K=2, h=0.5
#define NBPAIR 7     // batches per warp-pair
#define NCTA 293     // 2 pairs per CTA

typedef unsigned long long ull;

__device__ __forceinline__ ull ffma2(ull a, ull b, ull c) {
    ull d;
    asm("fma.rn.f32x2 %0, %1, %2, %3;" : "=l"(d) : "l"(a), "l"(b), "l"(c));
    return d;
}
__device__ __forceinline__ ull pk2(float x, float y) {
    ull r;
    asm("mov.b64 %0, {%1, %2};" : "=l"(r) : "f"(x), "f"(y));
    return r;
}
__device__ __forceinline__ void upk2(ull v, float &x, float &y) {
    asm("mov.b64 {%0, %1}, %2;" : "=f"(x), "=f"(y) : "l"(v));
}
__device__ __forceinline__ float sp_(float x) {
    return fmaxf(x, 0.f) + __logf(1.f + __expf(-fabsf(x)));
}
__device__ __forceinline__ float tanh_(float x) {
    float y;
    asm("tanh.approx.f32 %0, %1;" : "=f"(y) : "f"(x));
    return y;
}

#define BAR_ARRIVE(id) asm volatile("bar.arrive %0, 64;" :: "r"(id) : "memory")
#define BAR_SYNCN(id)  asm volatile("bar.sync %0, 64;"   :: "r"(id) : "memory")

// mm1 for NB batches starting at row sZb (stride 32), h1 -> sH1b
template<int NB>
__device__ __forceinline__ void mm1_run(const float* sZb, const ull* rw1, float rbf1,
                                        float* sH1b, int lane) {
    ull a1[NB];
#pragma unroll
    for (int k = 0; k < NB; k++) a1[k] = 0ull;
#pragma unroll
    for (int q = 0; q < 8; q++) {
#pragma unroll
        for (int k = 0; k < NB; k++) {
            ulonglong2 zq = *reinterpret_cast<const ulonglong2*>(sZb + k * 32 + 4 * q);
            a1[k] = ffma2(zq.x, rw1[2 * q], a1[k]);
            a1[k] = ffma2(zq.y, rw1[2 * q + 1], a1[k]);
        }
    }
#pragma unroll
    for (int k = 0; k < NB; k++) {
        float u, v; upk2(a1[k], u, v);
        sH1b[k * 32 + lane] = sp_(u + v + rbf1);
    }
}

// mm2 + tanh + einsum partial for TWO batches (NCH own channels)
template<int NCH>
__device__ __forceinline__ void mm2_two(const float* h0, const float* h1,
                                        const float* d0, const float* d1,
                                        const ull (*wreg)[16], const float* b2,
                                        float& r0, float& r1) {
    ull a0[NCH], a1[NCH];
#pragma unroll
    for (int c = 0; c < NCH; c++) { a0[c] = 0ull; a1[c] = 0ull; }
#pragma unroll
    for (int q = 0; q < 8; q++) {
        ulonglong2 hq0 = *reinterpret_cast<const ulonglong2*>(h0 + 4 * q);
        ulonglong2 hq1 = *reinterpret_cast<const ulonglong2*>(h1 + 4 * q);
#pragma unroll
        for (int c = 0; c < NCH; c++) {
            a0[c] = ffma2(hq0.x, wreg[c][2 * q], a0[c]);
            a1[c] = ffma2(hq1.x, wreg[c][2 * q], a1[c]);
            a0[c] = ffma2(hq0.y, wreg[c][2 * q + 1], a0[c]);
            a1[c] = ffma2(hq1.y, wreg[c][2 * q + 1], a1[c]);
        }
    }
    float g0[NCH], g1[NCH];
#pragma unroll
    for (int c = 0; c < NCH; c++) {
        float u, v;
        upk2(a0[c], u, v); g0[c] = tanh_(u + v + b2[c]);
        upk2(a1[c], u, v); g1[c] = tanh_(u + v + b2[c]);
    }
    ull e0 = ffma2(pk2(g0[0], g0[1]), *reinterpret_cast<const ull*>(d0), 0ull);
    ull e1 = ffma2(pk2(g1[0], g1[1]), *reinterpret_cast<const ull*>(d1), 0ull);
    if (NCH == 4) {
        e0 = ffma2(pk2(g0[2], g0[3]), *reinterpret_cast<const ull*>(d0 + 2), e0);
        e1 = ffma2(pk2(g1[2], g1[3]), *reinterpret_cast<const ull*>(d1 + 2), e1);
    }
    float a, b;
    upk2(e0, a, b); r0 = a + b;
    upk2(e1, a, b); r1 = a + b;
    if (NCH == 3) {
        r0 = fmaf(g0[2], d0[2], r0);
        r1 = fmaf(g1[2], d1[2], r1);
    }
}

// single-batch variant
template<int NCH>
__device__ __forceinline__ float mm2_one(const float* h0, const float* d0,
                                         const ull (*wreg)[16], const float* b2) {
    ull a0[NCH];
#pragma unroll
    for (int c = 0; c < NCH; c++) a0[c] = 0ull;
#pragma unroll
    for (int q = 0; q < 8; q++) {
        ulonglong2 hq0 = *reinterpret_cast<const ulonglong2*>(h0 + 4 * q);
#pragma unroll
        for (int c = 0; c < NCH; c++) {
            a0[c] = ffma2(hq0.x, wreg[c][2 * q], a0[c]);
            a0[c] = ffma2(hq0.y, wreg[c][2 * q + 1], a0[c]);
        }
    }
    float g0[NCH];
#pragma unroll
    for (int c = 0; c < NCH; c++) {
        float u, v; upk2(a0[c], u, v);
        g0[c] = tanh_(u + v + b2[c]);
    }
    ull e0 = ffma2(pk2(g0[0], g0[1]), *reinterpret_cast<const ull*>(d0), 0ull);
    if (NCH == 4) e0 = ffma2(pk2(g0[2], g0[3]), *reinterpret_cast<const ull*>(d0 + 2), e0);
    float a, b; upk2(e0, a, b);
    float r = a + b;
    if (NCH == 3) r = fmaf(g0[2], d0[2], r);
    return r;
}

__global__ __launch_bounds__(128, 2)
void cde_kernel(const float* __restrict__ X,      // (4096,64,7)
                const float* __restrict__ Winit,  // (32,7)
                const float* __restrict__ binit,  // (32)
                const float* __restrict__ Wf1,    // (32,32)
                const float* __restrict__ bf1,    // (32)
                const float* __restrict__ Wf2,    // (224,32)
                const float* __restrict__ bf2,    // (224)
                const float* __restrict__ Wo1,    // (16,32)
                const float* __restrict__ bo1,    // (16)
                const float* __restrict__ Wo2,    // (3,16)
                const float* __restrict__ bo2,    // (3)
                float* __restrict__ out)          // (4096,3)
{
    // 4 warps = 2 pairs; pair serves 7 batches.
    // Warp A (isB=0): channels {0..3} (NCH=4), batches {0,1}   (nb=2)
    // Warp B (isB=1): channels {4,5,6} (NCH=3), batches {2..6} (nb=5)
    __shared__ __align__(16) float sZ[2][8][32];      // zs per batch slot (owner-written)
    __shared__ __align__(16) float sH1[2][8][32];     // h1 (owner-written)
    __shared__ __align__(16) float sDX[2][3][8][8];   // spline values
    __shared__ __align__(16) float sPartX[2][8][32];  // partner-written einsum partials

    const int tid  = threadIdx.x;
    const int w    = tid >> 5;
    const int lane = tid & 31;          // = h
    const int pair = w >> 1;
    const int isB  = w & 1;
    const int gpair = blockIdx.x * 2 + pair;
    const int pairbase = gpair * NBPAIR;

    const int b0  = isB ? 2 : 0;
    const int nb  = isB ? 5 : 2;
    const int c0  = isB ? 4 : 0;        // first owned channel
    const int nch = isB ? 3 : 4;
    // named barriers (count 64 = 32 arrive + 32 sync):
    //  b1: B h1 chunk {2,3,4} -> A     b2: B h1 chunk {5,6} -> A
    //  b3: A h1 {0,1} -> B
    //  b4: B partials -> A             b5: A partials -> B
    const int base = pair * 5;

    // ---- Wf2 owned channels, j-pair packed, in registers ----
    ull wreg[4][16];
    float b2[4];
#pragma unroll
    for (int cp = 0; cp < 4; cp++) {
        if (cp < nch) {
            int cg = c0 + cp;
            const float2* wp = reinterpret_cast<const float2*>(Wf2 + (lane * C + cg) * 32);
#pragma unroll
            for (int jp = 0; jp < 16; jp++) { float2 v = __ldg(wp + jp); wreg[cp][jp] = pk2(v.x, v.y); }
            b2[cp] = __ldg(bf2 + lane * C + cg);
        } else {
#pragma unroll
            for (int jp = 0; jp < 16; jp++) wreg[cp][jp] = 0ull;
            b2[cp] = 0.f;
        }
    }
    ull rw1[16];
    {
        const float2* p1 = reinterpret_cast<const float2*>(Wf1 + lane * 32);
#pragma unroll
        for (int jp = 0; jp < 16; jp++) { float2 v = __ldg(p1 + jp); rw1[jp] = pk2(v.x, v.y); }
    }
    const float rbf1 = __ldg(bf1 + lane);

    // spline mapping: A writes dX rows 0-3, B rows 4-7 (row 7 dummy)
    const int db = lane >> 3;
    const int dc = lane & 7;
    const int srow = isB * 4 + db;
    const int sbatch = min(pairbase + srow, 4095);
    const float* xrow = X + (size_t)sbatch * (L * C) + ((dc < C) ? dc : 0);

    // z0 for own batches
    float z[5], ksum[5];
#pragma unroll
    for (int k = 0; k < 5; k++) { z[k] = 0.f; ksum[k] = 0.f; }
    for (int k = 0; k < nb; k++) {
        int gb = min(pairbase + b0 + k, 4095);
        float acc = __ldg(binit + lane);
        const float* xp = X + (size_t)gb * (L * C);
#pragma unroll
        for (int c = 0; c < C; c++) acc = fmaf(__ldg(xp + c), __ldg(Winit + lane * C + c), acc);
        z[k] = acc;
        sZ[pair][b0 + k][lane] = acc;
    }

    // initial dX(t=0) -> slot 0  (idx=0,f=0 -> diff)
    {
        float v = 0.f;
        if (dc < C) v = __ldg(xrow + C) - __ldg(xrow);
        sDX[pair][0][srow][dc] = v;
    }
    __syncthreads();

    // stencil carry registers (updated on even i)
    float st_diff = 0.f, st_m0 = 0.f, st_dm = 0.f;

#pragma unroll 1
    for (int i = 0; i < NSTEPS; i++) {
        // ---- spline: stencil advances only on even i; m1 == diff algebraically ----
        {
            if (!(i & 1)) {
                const int m = i >> 1;
                const float* p = xrow + m * C;
                float xm1 = 0.f, x0 = 0.f, x1 = 0.f;
                if (dc < C) {
                    x0 = __ldg(p);
                    x1 = __ldg(p + C);
                    if (m > 0) xm1 = __ldg(p - C);
                }
                st_diff = x1 - x0;
                st_m0 = (m > 0) ? (x0 - xm1) : st_diff;
                st_dm = st_diff - st_m0;
            }
            // eval(f) = m0 + dm * f * (4 - 3f);  f=0.25->0.8125, 0.5->1.25, 0.75->1.3125
            float fac = (i & 1) ? 1.3125f : 0.8125f;
            float vb = fmaf(st_dm, fac, st_m0);
            float vc = (i & 1) ? st_diff : fmaf(st_dm, 1.25f, st_m0);
            sDX[pair][2][srow][dc] = vb;
            sDX[pair][(i + 1) & 1][srow][dc] = vc;
        }
        const int slotA = i & 1, slotC = (i + 1) & 1;

#pragma unroll 1
        for (int s = 0; s < 4; s++) {
            const int slot = (s == 0) ? slotA : ((s == 3) ? slotC : 2);
            const float* dxs = &sDX[pair][slot][0][0];   // rows of 8
            float* sPx = &sPartX[pair][0][0];
            const float* h1t = &sH1[pair][0][0];

            __syncwarp();
            const float wk = (s == 1 || s == 2) ? 2.f : 1.f;
            const float an = (s < 2) ? 0.25f : 0.5f;

            if (!isB) {
                // ---- A: mm1 {0,1} -> publish -> mm2 own (regs) -> consume B chunks ----
                mm1_run<2>(&sZ[pair][0][0], rw1, rbf1, &sH1[pair][0][0], lane);
                BAR_ARRIVE(base + 3);
                float own0, own1;
                mm2_two<4>(h1t, h1t + 32, dxs, dxs + 8, wreg, b2, own0, own1);
                BAR_SYNCN(base + 1);          // B h1 {2,3,4} ready
                {
                    float r0, r1;
                    mm2_two<4>(h1t + 64, h1t + 96, dxs + 16, dxs + 24, wreg, b2, r0, r1);
                    sPx[64 + lane] = r0; sPx[96 + lane] = r1;
                    sPx[128 + lane] = mm2_one<4>(h1t + 128, dxs + 32, wreg, b2);
                }
                BAR_SYNCN(base + 2);          // B h1 {5,6} ready
                {
                    float r0, r1;
                    mm2_two<4>(h1t + 160, h1t + 192, dxs + 40, dxs + 48, wreg, b2, r0, r1);
                    sPx[160 + lane] = r0; sPx[192 + lane] = r1;
                }
                BAR_ARRIVE(base + 5);         // my partials (rows 2-6) -> B
                BAR_SYNCN(base + 4);          // B partials (rows 0-1) -> me

                // combine + RK4 for batches {0,1}
                float kk0 = own0 + sPx[lane];
                float kk1 = own1 + sPx[32 + lane];
                ksum[0] = fmaf(wk, kk0, ksum[0]);
                ksum[1] = fmaf(wk, kk1, ksum[1]);
                float z0v, z1v;
                if (s < 3) {
                    z0v = fmaf(an, kk0, z[0]);
                    z1v = fmaf(an, kk1, z[1]);
                } else {
                    z[0] = fmaf(ksum[0], (1.f / 12.f), z[0]); ksum[0] = 0.f; z0v = z[0];
                    z[1] = fmaf(ksum[1], (1.f / 12.f), z[1]); ksum[1] = 0.f; z1v = z[1];
                }
                sZ[pair][0][lane] = z0v;
                sZ[pair][1][lane] = z1v;
            } else {
                // ---- B: mm1 chunk {2,3,4} -> publish; chunk {5,6} -> publish ----
                mm1_run<3>(&sZ[pair][2][0], rw1, rbf1, &sH1[pair][2][0], lane);
                BAR_ARRIVE(base + 1);
                mm1_run<2>(&sZ[pair][5][0], rw1, rbf1, &sH1[pair][5][0], lane);
                BAR_ARRIVE(base + 2);
                float ownp[5];
                {   // mm2 own batches {2..6}, channels {4,5,6} (results stay in regs)
                    mm2_two<3>(h1t + 64, h1t + 96, dxs + 16 + 4, dxs + 24 + 4, wreg, b2, ownp[0], ownp[1]);
                    mm2_two<3>(h1t + 128, h1t + 160, dxs + 32 + 4, dxs + 40 + 4, wreg, b2, ownp[2], ownp[3]);
                    ownp[4] = mm2_one<3>(h1t + 192, dxs + 48 + 4, wreg, b2);
                }
                BAR_SYNCN(base + 3);          // A h1 {0,1} ready
                {
                    float r0, r1;
                    mm2_two<3>(h1t, h1t + 32, dxs + 4, dxs + 8 + 4, wreg, b2, r0, r1);
                    sPx[lane] = r0; sPx[32 + lane] = r1;
                }
                BAR_ARRIVE(base + 4);         // my partials (rows 0-1) -> A
                BAR_SYNCN(base + 5);          // A partials (rows 2-6) -> me

                // combine + RK4 for batches {2..6}
#pragma unroll
                for (int k = 0; k < 5; k++) {
                    int bs = 2 + k;
                    float kk = ownp[k] + sPx[bs * 32 + lane];
                    ksum[k] = fmaf(wk, kk, ksum[k]);
                    float zsv;
                    if (s < 3) {
                        zsv = fmaf(an, kk, z[k]);
                    } else {
                        z[k] = fmaf(ksum[k], (1.f / 12.f), z[k]);
                        ksum[k] = 0.f;
                        zsv = z[k];
                    }
                    sZ[pair][bs][lane] = zsv;
                }
            }
        }
    }

    __syncthreads();   // drain before scratch reuse

    // ---- output head (own batches) ----
    __syncwarp();
    // disjoint scratch: A rows 0-1, B rows 2-6 of sPartX[pair]
    float* so = &sPartX[pair][b0][0];
    if (lane < 16) {
        for (int k = 0; k < nb; k++) {
            float acc = __ldg(bo1 + lane);
#pragma unroll
            for (int hh = 0; hh < 32; hh++)
                acc = fmaf(sZ[pair][b0 + k][hh], __ldg(Wo1 + lane * 32 + hh), acc);
            so[k * 32 + lane] = sp_(acc);
        }
    }
    __syncwarp();
    if (lane < 3 * nb) {
        int k = lane / 3;
        int jo = lane - 3 * k;
        int gb = pairbase + b0 + k;
        if (gb < 4096) {
            float acc = __ldg(bo2 + jo);
#pragma unroll
            for (int i2 = 0; i2 < 16; i2++)
                acc = fmaf(so[k * 32 + i2], __ldg(Wo2 + jo * 16 + i2), acc);
            out[(size_t)gb * 3 + jo] = acc;
        }
    }
}

extern "C" void kernel_launch(void* const* d_in, const int* in_sizes, int n_in,
                              void* d_out, int out_size) {
    const float* X     = (const float*)d_in[0];
    const float* Winit = (const float*)d_in[1];
    const float* binit = (const float*)d_in[2];
    const float* Wf1   = (const float*)d_in[3];
    const float* bf1   = (const float*)d_in[4];
    const float* Wf2   = (const float*)d_in[5];
    const float* bf2   = (const float*)d_in[6];
    const float* Wo1   = (const float*)d_in[7];
    const float* bo1   = (const float*)d_in[8];
    const float* Wo2   = (const float*)d_in[9];
    const float* bo2   = (const float*)d_in[10];
    float* out = (float*)d_out;

    // 293 CTAs x 128 thr: 2 pairs/CTA x 7 batches = 4102 slots >= 4096 (tail guarded)
    cde_kernel<<<NCTA, 128>>>(X, Winit, binit, Wf1, bf1, Wf2, bf2,
                              Wo1, bo1, Wo2, bo2, out);
}